// round 15
// baseline (speedup 1.0000x reference)
#include <cuda_runtime.h>
#include <cuda_fp16.h>
#include <math.h>

#define BB 16
#define CC 256
#define HH 128
#define WW 128
#define HWp (HH*WW)          // 16384
#define HW4 (HWp/4)          // 4096

// Scratch (device globals — no allocations allowed)
// g_sf / g_samp are INTERLEAVED: float2 (avg,max) per pixel, [B][HW]
__device__ __align__(16) float  g_sf[BB*HWp*2];
__device__ __align__(16) __half g_h1h[BB*HWp*16];   // pixel-major fp16 [B,HW,16]
__device__ __align__(16) float  g_samp[BB*HWp*2];
__device__ __align__(16) float  g_w2eff[2*9*16];    // transposed [d][wo][ic]
__device__ float g_b2eff[2];

// ---------------------------------------------------------------------------
// Kernel 1: channel reduce (avg+max over C=256), 4-way split-channel within
// thread quads, shfl combine. Output interleaved float2 (avg,max).
// ---------------------------------------------------------------------------
__global__ void k_reduce(const float* __restrict__ x) {
    int idx = blockIdx.x * blockDim.x + threadIdx.x;   // 0..262143
    int q      = idx & 3;                              // channel group
    int pixel4 = idx >> 2;                             // 0..65535
    int b  = pixel4 >> 12;
    int p4 = pixel4 & 4095;

    const float4* xp = reinterpret_cast<const float4*>(x)
                     + (size_t)b * CC * HW4 + (size_t)(q * 64) * HW4 + p4;

    float4 s = make_float4(0.f, 0.f, 0.f, 0.f);
    float4 m = make_float4(-1e30f, -1e30f, -1e30f, -1e30f);
    #pragma unroll 32
    for (int c = 0; c < 64; ++c) {
        float4 v = __ldg(xp + (size_t)c * HW4);
        s.x += v.x; s.y += v.y; s.z += v.z; s.w += v.w;
        m.x = fmaxf(m.x, v.x); m.y = fmaxf(m.y, v.y);
        m.z = fmaxf(m.z, v.z); m.w = fmaxf(m.w, v.w);
    }

    #pragma unroll
    for (int d = 1; d <= 2; d <<= 1) {
        s.x += __shfl_xor_sync(0xffffffffu, s.x, d);
        s.y += __shfl_xor_sync(0xffffffffu, s.y, d);
        s.z += __shfl_xor_sync(0xffffffffu, s.z, d);
        s.w += __shfl_xor_sync(0xffffffffu, s.w, d);
        m.x = fmaxf(m.x, __shfl_xor_sync(0xffffffffu, m.x, d));
        m.y = fmaxf(m.y, __shfl_xor_sync(0xffffffffu, m.y, d));
        m.z = fmaxf(m.z, __shfl_xor_sync(0xffffffffu, m.z, d));
        m.w = fmaxf(m.w, __shfl_xor_sync(0xffffffffu, m.w, d));
    }

    if (q == 0) {
        const float inv = 1.0f / (float)CC;
        float4* o = reinterpret_cast<float4*>(g_sf);
        size_t f4 = ((size_t)b * HWp + p4 * 4) >> 1;
        o[f4]     = make_float4(s.x * inv, m.x, s.y * inv, m.y);
        o[f4 + 1] = make_float4(s.z * inv, m.z, s.w * inv, m.w);
    }
}

// ---------------------------------------------------------------------------
// Kernel 2: conv3x3 (2->16) + BN + ReLU. Thread = PIXEL PAIR (xp, xp+1):
// 3 rows x 4 guarded float2 loads = 12 loads per 2 px (was 18/px).
// Output fp16 pixel-major: 4 contiguous STG.128.
// Block 0 ALSO computes the group-averaged w2/b2 (strided over blockDim).
// ---------------------------------------------------------------------------
__global__ void k_conv1(const float* __restrict__ w1,
                        const float* __restrict__ gamma, const float* __restrict__ beta,
                        const float* __restrict__ mean,  const float* __restrict__ var,
                        const float* __restrict__ w2,    const float* __restrict__ b2) {
    __shared__ float ws[288];
    __shared__ float sc[16], bi[16];
    int t = threadIdx.x;
    for (int i = t; i < 288; i += blockDim.x) ws[i] = w1[i];
    if (t < 16) {
        float s = gamma[t] * rsqrtf(var[t] + 1e-5f);
        sc[t] = s;
        bi[t] = beta[t] - mean[t] * s;
    }

    if (blockIdx.x == 0) {
        for (int i = t; i < 288; i += blockDim.x) {
            int d  = i / 144;
            int r  = i % 144;
            int wo = r / 16;
            int ic = r % 16;
            float s = 0.f;
            #pragma unroll 7
            for (int j = 0; j < 49; ++j)
                s += w2[(size_t)(d * 49 + j) * 144 + ic * 9 + wo];
            g_w2eff[i] = s * (1.0f / 49.0f);
        }
        if (t < 2) {
            float s = 0.f;
            #pragma unroll 7
            for (int j = 0; j < 49; ++j) s += b2[t * 49 + j];
            g_b2eff[t] = s * (1.0f / 49.0f);
        }
    }
    __syncthreads();

    int pairi = blockIdx.x * blockDim.x + t;   // 0..131071
    int b     = pairi >> 13;
    int rem2  = pairi & 8191;
    int y  = rem2 >> 6;
    int xp = (rem2 & 63) << 1;                 // even column

    const float2* sf2 = reinterpret_cast<const float2*>(g_sf) + (size_t)b * HWp;

    // c[ch][row][col], cols = xp-1 .. xp+2
    float ca[3][4], cm[3][4];
    #pragma unroll
    for (int r = 0; r < 3; ++r) {
        int yy = y + r - 1;
        #pragma unroll
        for (int dxc = 0; dxc < 4; ++dxc) {
            int xx = xp + dxc - 1;
            float2 p = make_float2(0.f, 0.f);
            if (yy >= 0 && yy < HH && xx >= 0 && xx < WW)
                p = sf2[yy * WW + xx];
            ca[r][dxc] = p.x;
            cm[r][dxc] = p.y;
        }
    }

    __align__(16) __half2 ho[16];   // [px0: 8 half2][px1: 8 half2]
    #pragma unroll
    for (int p = 0; p < 8; ++p) {
        float a00 = 0.f, a01 = 0.f;   // oc=2p   : px0, px1
        float a10 = 0.f, a11 = 0.f;   // oc=2p+1 : px0, px1
        #pragma unroll
        for (int r = 0; r < 3; ++r)
            #pragma unroll
            for (int kw = 0; kw < 3; ++kw) {
                float wA0 = ws[(2 * p)     * 18 +     r * 3 + kw];  // ch0 (avg)
                float wM0 = ws[(2 * p)     * 18 + 9 + r * 3 + kw];  // ch1 (max)
                float wA1 = ws[(2 * p + 1) * 18 +     r * 3 + kw];
                float wM1 = ws[(2 * p + 1) * 18 + 9 + r * 3 + kw];
                float va0 = ca[r][kw],     vm0 = cm[r][kw];
                float va1 = ca[r][kw + 1], vm1 = cm[r][kw + 1];
                a00 = fmaf(va0, wA0, a00); a00 = fmaf(vm0, wM0, a00);
                a01 = fmaf(va1, wA0, a01); a01 = fmaf(vm1, wM0, a01);
                a10 = fmaf(va0, wA1, a10); a10 = fmaf(vm0, wM1, a10);
                a11 = fmaf(va1, wA1, a11); a11 = fmaf(vm1, wM1, a11);
            }
        float s0 = sc[2 * p], b0 = bi[2 * p];
        float s1 = sc[2 * p + 1], b1 = bi[2 * p + 1];
        ho[p]     = __floats2half2_rn(fmaxf(fmaf(a00, s0, b0), 0.f),
                                      fmaxf(fmaf(a10, s1, b1), 0.f));
        ho[8 + p] = __floats2half2_rn(fmaxf(fmaf(a01, s0, b0), 0.f),
                                      fmaxf(fmaf(a11, s1, b1), 0.f));
    }

    uint4* dst = reinterpret_cast<uint4*>(g_h1h) + ((size_t)b * HWp + y * WW + xp) * 2;
    const uint4* src = reinterpret_cast<const uint4*>(ho);
    dst[0] = src[0];
    dst[1] = src[1];
    dst[2] = src[2];
    dst[3] = src[3];
}

// ---------------------------------------------------------------------------
// Kernel 3: conv3x3 (16->2 eff) + bias, tanh*0.5, grid, bilinear sample.
// Thread = (8-channel half q) x (pixel pair xp,xp+1): 3x4 neighborhood,
// 12 uint4 loads per 2 pixels. Weight vectors shared across the pair.
// ---------------------------------------------------------------------------
__global__ void k_off_sample() {
    __shared__ float4 ws4[72];     // transposed [d][wo][16] as float4s
    __shared__ float b2s[2];
    int t = threadIdx.x;
    if (t < 72) ws4[t] = reinterpret_cast<const float4*>(g_w2eff)[t];
    if (t < 2)  b2s[t] = g_b2eff[t];
    __syncthreads();

    int idx   = blockIdx.x * blockDim.x + t;   // 0..262143
    int q     = idx & 1;                       // half: channels 8q..8q+7
    int pairi = idx >> 1;                      // 0..131071 pixel pairs
    int b     = pairi >> 13;
    int rem2  = pairi & 8191;
    int y  = rem2 >> 6;
    int xp = (rem2 & 63) << 1;                 // even column

    const uint4* hb = reinterpret_cast<const uint4*>(g_h1h) + (size_t)b * HWp * 2 + q;

    float ax0 = 0.f, ay0 = 0.f, ax1 = 0.f, ay1 = 0.f;

    #pragma unroll
    for (int dy = 0; dy < 3; ++dy) {
        int yy = y + dy - 1;
        if (yy < 0 || yy >= HH) continue;

        float c[4][8];
        #pragma unroll
        for (int dx = 0; dx < 4; ++dx) {
            int xx = xp + dx - 1;
            if (xx >= 0 && xx < WW) {
                uint4 hv = hb[(size_t)(yy * WW + xx) * 2];
                float2 f0 = __half22float2(*reinterpret_cast<__half2*>(&hv.x));
                float2 f1 = __half22float2(*reinterpret_cast<__half2*>(&hv.y));
                float2 f2 = __half22float2(*reinterpret_cast<__half2*>(&hv.z));
                float2 f3 = __half22float2(*reinterpret_cast<__half2*>(&hv.w));
                c[dx][0] = f0.x; c[dx][1] = f0.y;
                c[dx][2] = f1.x; c[dx][3] = f1.y;
                c[dx][4] = f2.x; c[dx][5] = f2.y;
                c[dx][6] = f3.x; c[dx][7] = f3.y;
            } else {
                #pragma unroll
                for (int k = 0; k < 8; ++k) c[dx][k] = 0.f;
            }
        }

        #pragma unroll
        for (int kw = 0; kw < 3; ++kw) {
            int wo = dy * 3 + kw;
            float4 wxa = ws4[wo * 4 + 2 * q],      wxb = ws4[wo * 4 + 2 * q + 1];
            float4 wya = ws4[36 + wo * 4 + 2 * q], wyb = ws4[36 + wo * 4 + 2 * q + 1];
            const float* p0 = c[kw];       // pixel xp
            const float* p1 = c[kw + 1];   // pixel xp+1
            ax0 = fmaf(p0[0], wxa.x, ax0); ax0 = fmaf(p0[1], wxa.y, ax0);
            ax0 = fmaf(p0[2], wxa.z, ax0); ax0 = fmaf(p0[3], wxa.w, ax0);
            ax0 = fmaf(p0[4], wxb.x, ax0); ax0 = fmaf(p0[5], wxb.y, ax0);
            ax0 = fmaf(p0[6], wxb.z, ax0); ax0 = fmaf(p0[7], wxb.w, ax0);
            ay0 = fmaf(p0[0], wya.x, ay0); ay0 = fmaf(p0[1], wya.y, ay0);
            ay0 = fmaf(p0[2], wya.z, ay0); ay0 = fmaf(p0[3], wya.w, ay0);
            ay0 = fmaf(p0[4], wyb.x, ay0); ay0 = fmaf(p0[5], wyb.y, ay0);
            ay0 = fmaf(p0[6], wyb.z, ay0); ay0 = fmaf(p0[7], wyb.w, ay0);
            ax1 = fmaf(p1[0], wxa.x, ax1); ax1 = fmaf(p1[1], wxa.y, ax1);
            ax1 = fmaf(p1[2], wxa.z, ax1); ax1 = fmaf(p1[3], wxa.w, ax1);
            ax1 = fmaf(p1[4], wxb.x, ax1); ax1 = fmaf(p1[5], wxb.y, ax1);
            ax1 = fmaf(p1[6], wxb.z, ax1); ax1 = fmaf(p1[7], wxb.w, ax1);
            ay1 = fmaf(p1[0], wya.x, ay1); ay1 = fmaf(p1[1], wya.y, ay1);
            ay1 = fmaf(p1[2], wya.z, ay1); ay1 = fmaf(p1[3], wya.w, ay1);
            ay1 = fmaf(p1[4], wyb.x, ay1); ay1 = fmaf(p1[5], wyb.y, ay1);
            ay1 = fmaf(p1[6], wyb.z, ay1); ay1 = fmaf(p1[7], wyb.w, ay1);
        }
    }

    ax0 += __shfl_xor_sync(0xffffffffu, ax0, 1);
    ay0 += __shfl_xor_sync(0xffffffffu, ay0, 1);
    ax1 += __shfl_xor_sync(0xffffffffu, ax1, 1);
    ay1 += __shfl_xor_sync(0xffffffffu, ay1, 1);

    if (q == 0) {
        const float2* sf2 = reinterpret_cast<const float2*>(g_sf) + (size_t)b * HWp;
        float res[4];
        #pragma unroll
        for (int j = 0; j < 2; ++j) {
            int x = xp + j;
            float ax = (j == 0 ? ax0 : ax1) + b2s[0];
            float ay = (j == 0 ? ay0 : ay1) + b2s[1];
            float txo = tanhf(ax) * 0.5f;
            float tyo = tanhf(ay) * 0.5f;
            float gxv = fmaf((float)x, 2.0f / 127.0f, -1.0f) + txo;
            float gyv = fmaf((float)y, 2.0f / 127.0f, -1.0f) + tyo;
            gxv = fminf(fmaxf(gxv, -1.f), 1.f);
            gyv = fminf(fmaxf(gyv, -1.f), 1.f);

            float ixf = ((gxv + 1.0f) * (float)WW - 1.0f) * 0.5f;
            float iyf = ((gyv + 1.0f) * (float)HH - 1.0f) * 0.5f;
            float x0f = floorf(ixf), y0f = floorf(iyf);
            int x0 = (int)x0f, y0 = (int)y0f;
            int x1 = x0 + 1,   y1 = y0 + 1;
            float wx1 = ixf - x0f, wx0 = 1.0f - wx1;
            float wy1 = iyf - y0f, wy0 = 1.0f - wy1;

            float w00 = wx0 * wy0, w10 = wx1 * wy0, w01 = wx0 * wy1, w11 = wx1 * wy1;
            bool vx0 = (x0 >= 0) & (x0 < WW), vx1 = (x1 >= 0) & (x1 < WW);
            bool vy0 = (y0 >= 0) & (y0 < HH), vy1 = (y1 >= 0) & (y1 < HH);

            float o0 = 0.f, o1 = 0.f;
            if (vy0 & vx0) { float2 v = sf2[y0 * WW + x0]; o0 = fmaf(v.x, w00, o0); o1 = fmaf(v.y, w00, o1); }
            if (vy0 & vx1) { float2 v = sf2[y0 * WW + x1]; o0 = fmaf(v.x, w10, o0); o1 = fmaf(v.y, w10, o1); }
            if (vy1 & vx0) { float2 v = sf2[y1 * WW + x0]; o0 = fmaf(v.x, w01, o0); o1 = fmaf(v.y, w01, o1); }
            if (vy1 & vx1) { float2 v = sf2[y1 * WW + x1]; o0 = fmaf(v.x, w11, o0); o1 = fmaf(v.y, w11, o1); }
            res[2 * j]     = o0;
            res[2 * j + 1] = o1;
        }
        reinterpret_cast<float4*>(g_samp)[((size_t)b * HWp + y * WW + xp) >> 1] =
            make_float4(res[0], res[1], res[2], res[3]);
    }
}

// ---------------------------------------------------------------------------
// Kernel 4: conv7x7 (2->1, pad 3) + sigmoid. ROW-SPLIT: 2 threads per pixel
// pair — lane r=0 takes dy 0..3, r=1 takes dy 4..6; shfl combine.
// Total loads unchanged, threads doubled to 262144.
// ---------------------------------------------------------------------------
__global__ void k_attn(const float* __restrict__ aw, float* __restrict__ out) {
    __shared__ float ws[98];
    int t = threadIdx.x;
    if (t < 98) ws[t] = aw[t];
    __syncthreads();

    int idx   = blockIdx.x * blockDim.x + t;   // 0..262143
    int r     = idx & 1;                       // row half
    int pairi = idx >> 1;                      // 0..131071
    int b     = pairi >> 13;
    int rem2  = pairi & 8191;
    int y     = rem2 >> 6;
    int ci    = rem2 & 63;                     // chunk = pixel pair index
    int xp    = ci << 1;

    const float4* sb4 = reinterpret_cast<const float4*>(g_samp) + (size_t)b * (HWp / 2);
    float a0 = 0.f, a1 = 0.f;

    #pragma unroll
    for (int dy = 0; dy < 7; ++dy) {
        if ((dy < 4) != (r == 0)) continue;    // partition rows across lane pair
        int yy = y + dy - 3;
        if (yy < 0 || yy >= HH) continue;
        const float4* row = sb4 + yy * 64;

        float4 c[5];
        #pragma unroll
        for (int j = 0; j < 5; ++j) {
            int cj = ci - 2 + j;
            c[j] = (cj >= 0 && cj < 64) ? row[cj] : make_float4(0.f, 0.f, 0.f, 0.f);
        }
        // columns xp-4 .. xp+5 ; cl0 = avg, cl1 = max
        float cl0[10], cl1[10];
        #pragma unroll
        for (int j = 0; j < 5; ++j) {
            cl0[2 * j]     = c[j].x; cl1[2 * j]     = c[j].y;
            cl0[2 * j + 1] = c[j].z; cl1[2 * j + 1] = c[j].w;
        }
        #pragma unroll
        for (int kw = 0; kw < 7; ++kw) {
            float w0 = ws[dy * 7 + kw];
            float w1 = ws[49 + dy * 7 + kw];
            a0 = fmaf(cl0[1 + kw], w0, a0);  // pixel xp
            a0 = fmaf(cl1[1 + kw], w1, a0);
            a1 = fmaf(cl0[2 + kw], w0, a1);  // pixel xp+1
            a1 = fmaf(cl1[2 + kw], w1, a1);
        }
    }

    a0 += __shfl_xor_sync(0xffffffffu, a0, 1);
    a1 += __shfl_xor_sync(0xffffffffu, a1, 1);

    if (r == 0) {
        float2 o;
        o.x = 1.0f / (1.0f + expf(-a0));
        o.y = 1.0f / (1.0f + expf(-a1));
        *reinterpret_cast<float2*>(out + (size_t)b * HWp + y * WW + xp) = o;
    }
}

// ---------------------------------------------------------------------------
extern "C" void kernel_launch(void* const* d_in, const int* in_sizes, int n_in,
                              void* d_out, int out_size) {
    const float* x     = (const float*)d_in[0];
    const float* w1    = (const float*)d_in[1];
    const float* gamma = (const float*)d_in[2];
    const float* beta  = (const float*)d_in[3];
    const float* mean  = (const float*)d_in[4];
    const float* var   = (const float*)d_in[5];
    const float* w2    = (const float*)d_in[6];
    const float* b2    = (const float*)d_in[7];
    const float* aw    = (const float*)d_in[8];
    float* out = (float*)d_out;

    k_reduce<<<1024, 256>>>(x);
    k_conv1<<<512, 256>>>(w1, gamma, beta, mean, var, w2, b2);
    k_off_sample<<<1024, 256>>>();
    k_attn<<<2048, 128>>>(aw, out);
}

// round 16
// speedup vs baseline: 1.0626x; 1.0626x over previous
#include <cuda_runtime.h>
#include <cuda_fp16.h>
#include <math.h>

#define BB 16
#define CC 256
#define HH 128
#define WW 128
#define HWp (HH*WW)          // 16384
#define HW4 (HWp/4)          // 4096

// Scratch (device globals — no allocations allowed)
// g_sf / g_samp are INTERLEAVED: float2 (avg,max) per pixel, [B][HW]
__device__ __align__(16) float  g_sf[BB*HWp*2];
__device__ __align__(16) __half g_h1h[BB*HWp*16];   // pixel-major fp16 [B,HW,16]
__device__ __align__(16) float  g_samp[BB*HWp*2];
__device__ __align__(16) float  g_w2eff[2*9*16];    // transposed [d][wo][ic]
__device__ float g_b2eff[2];

// ---------------------------------------------------------------------------
// Kernel 1: channel reduce (avg+max over C=256), 4-way split-channel within
// thread quads, shfl combine. Output interleaved float2 (avg,max).
// ---------------------------------------------------------------------------
__global__ void k_reduce(const float* __restrict__ x) {
    int idx = blockIdx.x * blockDim.x + threadIdx.x;   // 0..262143
    int q      = idx & 3;                              // channel group
    int pixel4 = idx >> 2;                             // 0..65535
    int b  = pixel4 >> 12;
    int p4 = pixel4 & 4095;

    const float4* xp = reinterpret_cast<const float4*>(x)
                     + (size_t)b * CC * HW4 + (size_t)(q * 64) * HW4 + p4;

    float4 s = make_float4(0.f, 0.f, 0.f, 0.f);
    float4 m = make_float4(-1e30f, -1e30f, -1e30f, -1e30f);
    #pragma unroll 32
    for (int c = 0; c < 64; ++c) {
        float4 v = __ldg(xp + (size_t)c * HW4);
        s.x += v.x; s.y += v.y; s.z += v.z; s.w += v.w;
        m.x = fmaxf(m.x, v.x); m.y = fmaxf(m.y, v.y);
        m.z = fmaxf(m.z, v.z); m.w = fmaxf(m.w, v.w);
    }

    #pragma unroll
    for (int d = 1; d <= 2; d <<= 1) {
        s.x += __shfl_xor_sync(0xffffffffu, s.x, d);
        s.y += __shfl_xor_sync(0xffffffffu, s.y, d);
        s.z += __shfl_xor_sync(0xffffffffu, s.z, d);
        s.w += __shfl_xor_sync(0xffffffffu, s.w, d);
        m.x = fmaxf(m.x, __shfl_xor_sync(0xffffffffu, m.x, d));
        m.y = fmaxf(m.y, __shfl_xor_sync(0xffffffffu, m.y, d));
        m.z = fmaxf(m.z, __shfl_xor_sync(0xffffffffu, m.z, d));
        m.w = fmaxf(m.w, __shfl_xor_sync(0xffffffffu, m.w, d));
    }

    if (q == 0) {
        const float inv = 1.0f / (float)CC;
        float4* o = reinterpret_cast<float4*>(g_sf);
        size_t f4 = ((size_t)b * HWp + p4 * 4) >> 1;
        o[f4]     = make_float4(s.x * inv, m.x, s.y * inv, m.y);
        o[f4 + 1] = make_float4(s.z * inv, m.z, s.w * inv, m.w);
    }
}

// ---------------------------------------------------------------------------
// Kernel 2: conv3x3 (2->16) + BN + ReLU. Thread = PIXEL PAIR (xp, xp+1):
// 3 rows x 4 guarded float2 loads = 12 loads per 2 px.
// Output fp16 pixel-major: 4 contiguous STG.128.
// Block 0 ALSO computes the group-averaged w2/b2 (strided over blockDim).
// ---------------------------------------------------------------------------
__global__ void k_conv1(const float* __restrict__ w1,
                        const float* __restrict__ gamma, const float* __restrict__ beta,
                        const float* __restrict__ mean,  const float* __restrict__ var,
                        const float* __restrict__ w2,    const float* __restrict__ b2) {
    __shared__ float ws[288];
    __shared__ float sc[16], bi[16];
    int t = threadIdx.x;
    for (int i = t; i < 288; i += blockDim.x) ws[i] = w1[i];
    if (t < 16) {
        float s = gamma[t] * rsqrtf(var[t] + 1e-5f);
        sc[t] = s;
        bi[t] = beta[t] - mean[t] * s;
    }

    if (blockIdx.x == 0) {
        for (int i = t; i < 288; i += blockDim.x) {
            int d  = i / 144;
            int r  = i % 144;
            int wo = r / 16;
            int ic = r % 16;
            float s = 0.f;
            #pragma unroll 7
            for (int j = 0; j < 49; ++j)
                s += w2[(size_t)(d * 49 + j) * 144 + ic * 9 + wo];
            g_w2eff[i] = s * (1.0f / 49.0f);
        }
        if (t < 2) {
            float s = 0.f;
            #pragma unroll 7
            for (int j = 0; j < 49; ++j) s += b2[t * 49 + j];
            g_b2eff[t] = s * (1.0f / 49.0f);
        }
    }
    __syncthreads();

    int pairi = blockIdx.x * blockDim.x + t;   // 0..131071
    int b     = pairi >> 13;
    int rem2  = pairi & 8191;
    int y  = rem2 >> 6;
    int xp = (rem2 & 63) << 1;                 // even column

    const float2* sf2 = reinterpret_cast<const float2*>(g_sf) + (size_t)b * HWp;

    // c[ch][row][col], cols = xp-1 .. xp+2
    float ca[3][4], cm[3][4];
    #pragma unroll
    for (int r = 0; r < 3; ++r) {
        int yy = y + r - 1;
        #pragma unroll
        for (int dxc = 0; dxc < 4; ++dxc) {
            int xx = xp + dxc - 1;
            float2 p = make_float2(0.f, 0.f);
            if (yy >= 0 && yy < HH && xx >= 0 && xx < WW)
                p = sf2[yy * WW + xx];
            ca[r][dxc] = p.x;
            cm[r][dxc] = p.y;
        }
    }

    __align__(16) __half2 ho[16];   // [px0: 8 half2][px1: 8 half2]
    #pragma unroll
    for (int p = 0; p < 8; ++p) {
        float a00 = 0.f, a01 = 0.f;   // oc=2p   : px0, px1
        float a10 = 0.f, a11 = 0.f;   // oc=2p+1 : px0, px1
        #pragma unroll
        for (int r = 0; r < 3; ++r)
            #pragma unroll
            for (int kw = 0; kw < 3; ++kw) {
                float wA0 = ws[(2 * p)     * 18 +     r * 3 + kw];
                float wM0 = ws[(2 * p)     * 18 + 9 + r * 3 + kw];
                float wA1 = ws[(2 * p + 1) * 18 +     r * 3 + kw];
                float wM1 = ws[(2 * p + 1) * 18 + 9 + r * 3 + kw];
                float va0 = ca[r][kw],     vm0 = cm[r][kw];
                float va1 = ca[r][kw + 1], vm1 = cm[r][kw + 1];
                a00 = fmaf(va0, wA0, a00); a00 = fmaf(vm0, wM0, a00);
                a01 = fmaf(va1, wA0, a01); a01 = fmaf(vm1, wM0, a01);
                a10 = fmaf(va0, wA1, a10); a10 = fmaf(vm0, wM1, a10);
                a11 = fmaf(va1, wA1, a11); a11 = fmaf(vm1, wM1, a11);
            }
        float s0 = sc[2 * p], b0 = bi[2 * p];
        float s1 = sc[2 * p + 1], b1 = bi[2 * p + 1];
        ho[p]     = __floats2half2_rn(fmaxf(fmaf(a00, s0, b0), 0.f),
                                      fmaxf(fmaf(a10, s1, b1), 0.f));
        ho[8 + p] = __floats2half2_rn(fmaxf(fmaf(a01, s0, b0), 0.f),
                                      fmaxf(fmaf(a11, s1, b1), 0.f));
    }

    uint4* dst = reinterpret_cast<uint4*>(g_h1h) + ((size_t)b * HWp + y * WW + xp) * 2;
    const uint4* src = reinterpret_cast<const uint4*>(ho);
    dst[0] = src[0];
    dst[1] = src[1];
    dst[2] = src[2];
    dst[3] = src[3];
}

// ---------------------------------------------------------------------------
// Kernel 3: conv3x3 (16->2 eff) + bias, tanh*0.5, grid, bilinear sample.
// Thread = (8-channel half q) x (pixel pair xp,xp+1): 3x4 neighborhood,
// 12 uint4 loads per 2 pixels. Weight vectors shared across the pair.
// ---------------------------------------------------------------------------
__global__ void k_off_sample() {
    __shared__ float4 ws4[72];     // transposed [d][wo][16] as float4s
    __shared__ float b2s[2];
    int t = threadIdx.x;
    if (t < 72) ws4[t] = reinterpret_cast<const float4*>(g_w2eff)[t];
    if (t < 2)  b2s[t] = g_b2eff[t];
    __syncthreads();

    int idx   = blockIdx.x * blockDim.x + t;   // 0..262143
    int q     = idx & 1;                       // half: channels 8q..8q+7
    int pairi = idx >> 1;                      // 0..131071 pixel pairs
    int b     = pairi >> 13;
    int rem2  = pairi & 8191;
    int y  = rem2 >> 6;
    int xp = (rem2 & 63) << 1;                 // even column

    const uint4* hb = reinterpret_cast<const uint4*>(g_h1h) + (size_t)b * HWp * 2 + q;

    float ax0 = 0.f, ay0 = 0.f, ax1 = 0.f, ay1 = 0.f;

    #pragma unroll
    for (int dy = 0; dy < 3; ++dy) {
        int yy = y + dy - 1;
        if (yy < 0 || yy >= HH) continue;

        float c[4][8];
        #pragma unroll
        for (int dx = 0; dx < 4; ++dx) {
            int xx = xp + dx - 1;
            if (xx >= 0 && xx < WW) {
                uint4 hv = hb[(size_t)(yy * WW + xx) * 2];
                float2 f0 = __half22float2(*reinterpret_cast<__half2*>(&hv.x));
                float2 f1 = __half22float2(*reinterpret_cast<__half2*>(&hv.y));
                float2 f2 = __half22float2(*reinterpret_cast<__half2*>(&hv.z));
                float2 f3 = __half22float2(*reinterpret_cast<__half2*>(&hv.w));
                c[dx][0] = f0.x; c[dx][1] = f0.y;
                c[dx][2] = f1.x; c[dx][3] = f1.y;
                c[dx][4] = f2.x; c[dx][5] = f2.y;
                c[dx][6] = f3.x; c[dx][7] = f3.y;
            } else {
                #pragma unroll
                for (int k = 0; k < 8; ++k) c[dx][k] = 0.f;
            }
        }

        #pragma unroll
        for (int kw = 0; kw < 3; ++kw) {
            int wo = dy * 3 + kw;
            float4 wxa = ws4[wo * 4 + 2 * q],      wxb = ws4[wo * 4 + 2 * q + 1];
            float4 wya = ws4[36 + wo * 4 + 2 * q], wyb = ws4[36 + wo * 4 + 2 * q + 1];
            const float* p0 = c[kw];       // pixel xp
            const float* p1 = c[kw + 1];   // pixel xp+1
            ax0 = fmaf(p0[0], wxa.x, ax0); ax0 = fmaf(p0[1], wxa.y, ax0);
            ax0 = fmaf(p0[2], wxa.z, ax0); ax0 = fmaf(p0[3], wxa.w, ax0);
            ax0 = fmaf(p0[4], wxb.x, ax0); ax0 = fmaf(p0[5], wxb.y, ax0);
            ax0 = fmaf(p0[6], wxb.z, ax0); ax0 = fmaf(p0[7], wxb.w, ax0);
            ay0 = fmaf(p0[0], wya.x, ay0); ay0 = fmaf(p0[1], wya.y, ay0);
            ay0 = fmaf(p0[2], wya.z, ay0); ay0 = fmaf(p0[3], wya.w, ay0);
            ay0 = fmaf(p0[4], wyb.x, ay0); ay0 = fmaf(p0[5], wyb.y, ay0);
            ay0 = fmaf(p0[6], wyb.z, ay0); ay0 = fmaf(p0[7], wyb.w, ay0);
            ax1 = fmaf(p1[0], wxa.x, ax1); ax1 = fmaf(p1[1], wxa.y, ax1);
            ax1 = fmaf(p1[2], wxa.z, ax1); ax1 = fmaf(p1[3], wxa.w, ax1);
            ax1 = fmaf(p1[4], wxb.x, ax1); ax1 = fmaf(p1[5], wxb.y, ax1);
            ax1 = fmaf(p1[6], wxb.z, ax1); ax1 = fmaf(p1[7], wxb.w, ax1);
            ay1 = fmaf(p1[0], wya.x, ay1); ay1 = fmaf(p1[1], wya.y, ay1);
            ay1 = fmaf(p1[2], wya.z, ay1); ay1 = fmaf(p1[3], wya.w, ay1);
            ay1 = fmaf(p1[4], wyb.x, ay1); ay1 = fmaf(p1[5], wyb.y, ay1);
            ay1 = fmaf(p1[6], wyb.z, ay1); ay1 = fmaf(p1[7], wyb.w, ay1);
        }
    }

    ax0 += __shfl_xor_sync(0xffffffffu, ax0, 1);
    ay0 += __shfl_xor_sync(0xffffffffu, ay0, 1);
    ax1 += __shfl_xor_sync(0xffffffffu, ax1, 1);
    ay1 += __shfl_xor_sync(0xffffffffu, ay1, 1);

    if (q == 0) {
        const float2* sf2 = reinterpret_cast<const float2*>(g_sf) + (size_t)b * HWp;
        float res[4];
        #pragma unroll
        for (int j = 0; j < 2; ++j) {
            int x = xp + j;
            float ax = (j == 0 ? ax0 : ax1) + b2s[0];
            float ay = (j == 0 ? ay0 : ay1) + b2s[1];
            float txo = tanhf(ax) * 0.5f;
            float tyo = tanhf(ay) * 0.5f;
            float gxv = fmaf((float)x, 2.0f / 127.0f, -1.0f) + txo;
            float gyv = fmaf((float)y, 2.0f / 127.0f, -1.0f) + tyo;
            gxv = fminf(fmaxf(gxv, -1.f), 1.f);
            gyv = fminf(fmaxf(gyv, -1.f), 1.f);

            float ixf = ((gxv + 1.0f) * (float)WW - 1.0f) * 0.5f;
            float iyf = ((gyv + 1.0f) * (float)HH - 1.0f) * 0.5f;
            float x0f = floorf(ixf), y0f = floorf(iyf);
            int x0 = (int)x0f, y0 = (int)y0f;
            int x1 = x0 + 1,   y1 = y0 + 1;
            float wx1 = ixf - x0f, wx0 = 1.0f - wx1;
            float wy1 = iyf - y0f, wy0 = 1.0f - wy1;

            float w00 = wx0 * wy0, w10 = wx1 * wy0, w01 = wx0 * wy1, w11 = wx1 * wy1;
            bool vx0 = (x0 >= 0) & (x0 < WW), vx1 = (x1 >= 0) & (x1 < WW);
            bool vy0 = (y0 >= 0) & (y0 < HH), vy1 = (y1 >= 0) & (y1 < HH);

            float o0 = 0.f, o1 = 0.f;
            if (vy0 & vx0) { float2 v = sf2[y0 * WW + x0]; o0 = fmaf(v.x, w00, o0); o1 = fmaf(v.y, w00, o1); }
            if (vy0 & vx1) { float2 v = sf2[y0 * WW + x1]; o0 = fmaf(v.x, w10, o0); o1 = fmaf(v.y, w10, o1); }
            if (vy1 & vx0) { float2 v = sf2[y1 * WW + x0]; o0 = fmaf(v.x, w01, o0); o1 = fmaf(v.y, w01, o1); }
            if (vy1 & vx1) { float2 v = sf2[y1 * WW + x1]; o0 = fmaf(v.x, w11, o0); o1 = fmaf(v.y, w11, o1); }
            res[2 * j]     = o0;
            res[2 * j + 1] = o1;
        }
        reinterpret_cast<float4*>(g_samp)[((size_t)b * HWp + y * WW + xp) >> 1] =
            make_float4(res[0], res[1], res[2], res[3]);
    }
}

// ---------------------------------------------------------------------------
// Kernel 4: conv7x7 (2->1, pad 3) + sigmoid. 2 px/thread, 131072 threads
// (R13 measured optimum). 5 float4 chunks/row.
// ---------------------------------------------------------------------------
__global__ void k_attn(const float* __restrict__ aw, float* __restrict__ out) {
    __shared__ float ws[98];
    int t = threadIdx.x;
    if (t < 98) ws[t] = aw[t];
    __syncthreads();

    int idx  = blockIdx.x * blockDim.x + t;    // 0..131071
    int b    = idx >> 13;
    int rem2 = idx & 8191;
    int y    = rem2 >> 6;
    int ci   = rem2 & 63;                      // chunk = pixel pair index
    int xp   = ci << 1;

    const float4* sb4 = reinterpret_cast<const float4*>(g_samp) + (size_t)b * (HWp / 2);
    float a0 = 0.f, a1 = 0.f;

    #pragma unroll
    for (int dy = 0; dy < 7; ++dy) {
        int yy = y + dy - 3;
        if (yy < 0 || yy >= HH) continue;
        const float4* row = sb4 + yy * 64;

        float4 c[5];
        #pragma unroll
        for (int j = 0; j < 5; ++j) {
            int cj = ci - 2 + j;
            c[j] = (cj >= 0 && cj < 64) ? row[cj] : make_float4(0.f, 0.f, 0.f, 0.f);
        }
        // columns xp-4 .. xp+5 ; cl0 = avg, cl1 = max
        float cl0[10], cl1[10];
        #pragma unroll
        for (int j = 0; j < 5; ++j) {
            cl0[2 * j]     = c[j].x; cl1[2 * j]     = c[j].y;
            cl0[2 * j + 1] = c[j].z; cl1[2 * j + 1] = c[j].w;
        }
        #pragma unroll
        for (int kw = 0; kw < 7; ++kw) {
            float w0 = ws[dy * 7 + kw];
            float w1 = ws[49 + dy * 7 + kw];
            a0 = fmaf(cl0[1 + kw], w0, a0);  // pixel xp:   col xp-3+kw
            a0 = fmaf(cl1[1 + kw], w1, a0);
            a1 = fmaf(cl0[2 + kw], w0, a1);  // pixel xp+1
            a1 = fmaf(cl1[2 + kw], w1, a1);
        }
    }

    float2 o;
    o.x = 1.0f / (1.0f + expf(-a0));
    o.y = 1.0f / (1.0f + expf(-a1));
    *reinterpret_cast<float2*>(out + (size_t)b * HWp + y * WW + xp) = o;
}

// ---------------------------------------------------------------------------
extern "C" void kernel_launch(void* const* d_in, const int* in_sizes, int n_in,
                              void* d_out, int out_size) {
    const float* x     = (const float*)d_in[0];
    const float* w1    = (const float*)d_in[1];
    const float* gamma = (const float*)d_in[2];
    const float* beta  = (const float*)d_in[3];
    const float* mean  = (const float*)d_in[4];
    const float* var   = (const float*)d_in[5];
    const float* w2    = (const float*)d_in[6];
    const float* b2    = (const float*)d_in[7];
    const float* aw    = (const float*)d_in[8];
    float* out = (float*)d_out;

    k_reduce<<<2048, 128>>>(x);
    k_conv1<<<512, 256>>>(w1, gamma, beta, mean, var, w2, b2);
    k_off_sample<<<1024, 256>>>();
    k_attn<<<1024, 128>>>(aw, out);
}